// round 1
// baseline (speedup 1.0000x reference)
#include <cuda_runtime.h>

#define NB 4
#define NN 512
#define DD 128
#define H1C 64
#define H2C 32
#define TS 32
#define NTILES (NN / TS)                    // 16
#define NPAIRS (NTILES * (NTILES + 1) / 2)  // 136
#define NEG 0.1f

__device__ __forceinline__ unsigned long long pack2(float x, float y) {
    unsigned long long r;
    asm("mov.b64 %0, {%1, %2};" : "=l"(r) : "f"(x), "f"(y));
    return r;
}
__device__ __forceinline__ void ffma2(unsigned long long& acc,
                                      unsigned long long a,
                                      unsigned long long b) {
    // acc = a * b + acc  (packed f32x2)
    asm("fma.rn.f32x2 %0, %1, %2, %0;" : "+l"(acc) : "l"(a), "l"(b));
}
__device__ __forceinline__ float2 unpack2(unsigned long long v) {
    float2 f;
    asm("mov.b64 {%0, %1}, %2;" : "=f"(f.x), "=f"(f.y) : "l"(v));
    return f;
}
__device__ __forceinline__ float leaky(float x) {
    return x >= 0.0f ? x : NEG * x;
}

// ---------------------------------------------------------------------------
// Kernel 1: symmetric logits.  One block = one (tile_i, tile_j) pair with
// ti <= tj, for one batch.  128 threads, 8 pairs per thread.
// Warp w, lane l handles (ii = ti*32 + w + 4*p, jj = tj*32 + l), p = 0..7.
// vi loads are warp-broadcast; vj loads are lane-strided (L1-resident, 32KB).
// Weights live in shared, pre-transposed and packed for fma.rn.f32x2.
// ---------------------------------------------------------------------------
__global__ __launch_bounds__(128, 4)
void adj_logits_kernel(const float* __restrict__ v,
                       const float* __restrict__ W1, const float* __restrict__ b1,
                       const float* __restrict__ W2, const float* __restrict__ b2,
                       const float* __restrict__ W3, const float* __restrict__ b3,
                       float* __restrict__ out)
{
    __shared__ unsigned long long W1s[DD * H1C / 2];  // [d][o/2] pairs  (32 KB)
    __shared__ unsigned long long W2s[H1C * H2C / 2]; // [c][o/2] pairs  ( 8 KB)
    __shared__ float w3s[H2C];
    __shared__ unsigned long long b1s[H1C / 2];
    __shared__ unsigned long long b2s[H2C / 2];

    const int tid = threadIdx.x;

    // Load + transpose + pack weights.
    for (int idx = tid; idx < DD * H1C / 2; idx += 128) {
        int d  = idx / (H1C / 2);
        int op = idx % (H1C / 2);
        W1s[idx] = pack2(W1[(2 * op) * DD + d], W1[(2 * op + 1) * DD + d]);
    }
    for (int idx = tid; idx < H1C * H2C / 2; idx += 128) {
        int c  = idx / (H2C / 2);
        int op = idx % (H2C / 2);
        W2s[idx] = pack2(W2[(2 * op) * H1C + c], W2[(2 * op + 1) * H1C + c]);
    }
    if (tid < H2C)     w3s[tid] = W3[tid];
    if (tid < H1C / 2) b1s[tid] = pack2(b1[2 * tid], b1[2 * tid + 1]);
    if (tid < H2C / 2) b2s[tid] = pack2(b2[2 * tid], b2[2 * tid + 1]);
    const float bias3 = b3[0];
    __syncthreads();

    // Decode (ti, tj) with ti <= tj from blockIdx.x in [0, 136).
    const int b = blockIdx.y;
    int rem = blockIdx.x;
    int ti = 0;
    while (rem >= NTILES - ti) { rem -= NTILES - ti; ti++; }
    const int tj = ti + rem;

    const int warp = tid >> 5;
    const int lane = tid & 31;
    const int jj = tj * TS + lane;

    const float4* __restrict__ vbase = (const float4*)(v + (size_t)b * NN * DD);
    const float4* __restrict__ vj4 = vbase + (size_t)jj * (DD / 4);
    float* __restrict__ ob = out + (size_t)b * NN * NN;

    #pragma unroll 1
    for (int p = 0; p < 8; ++p) {
        const int ii = ti * TS + warp + 4 * p;
        const float4* __restrict__ vi4 = vbase + (size_t)ii * (DD / 4);

        // ---- layer 1: h1[64] = W1 @ |vi - vj| + b1 (packed pairs) ----
        unsigned long long h1[H1C / 2];
        #pragma unroll
        for (int q = 0; q < H1C / 2; ++q) h1[q] = b1s[q];

        #pragma unroll 2
        for (int dc = 0; dc < DD / 4; ++dc) {
            float4 a4 = vi4[dc];
            float4 c4 = vj4[dc];
            float ph[4];
            ph[0] = fabsf(a4.x - c4.x);
            ph[1] = fabsf(a4.y - c4.y);
            ph[2] = fabsf(a4.z - c4.z);
            ph[3] = fabsf(a4.w - c4.w);
            #pragma unroll
            for (int e = 0; e < 4; ++e) {
                unsigned long long ph2 = pack2(ph[e], ph[e]);
                const unsigned long long* wrow = &W1s[(dc * 4 + e) * (H1C / 2)];
                #pragma unroll
                for (int q = 0; q < H1C / 2; ++q) ffma2(h1[q], ph2, wrow[q]);
            }
        }

        // ---- layer 2: h2[32] = W2 @ leaky(h1) + b2 ----
        unsigned long long h2[H2C / 2];
        #pragma unroll
        for (int q = 0; q < H2C / 2; ++q) h2[q] = b2s[q];
        #pragma unroll
        for (int q = 0; q < H1C / 2; ++q) {
            float2 hv = unpack2(h1[q]);
            float c0 = leaky(hv.x);
            float c1 = leaky(hv.y);
            unsigned long long c02 = pack2(c0, c0);
            const unsigned long long* w0 = &W2s[(2 * q) * (H2C / 2)];
            #pragma unroll
            for (int r = 0; r < H2C / 2; ++r) ffma2(h2[r], c02, w0[r]);
            unsigned long long c12 = pack2(c1, c1);
            const unsigned long long* w1r = &W2s[(2 * q + 1) * (H2C / 2)];
            #pragma unroll
            for (int r = 0; r < H2C / 2; ++r) ffma2(h2[r], c12, w1r[r]);
        }

        // ---- layer 3: a = w3 . leaky(h2) + b3 ----
        float acc = bias3;
        #pragma unroll
        for (int q = 0; q < H2C / 2; ++q) {
            float2 hv = unpack2(h2[q]);
            acc += leaky(hv.x) * w3s[2 * q] + leaky(hv.y) * w3s[2 * q + 1];
        }

        // Symmetric writes (identical value for (ii,jj) and (jj,ii)).
        ob[(size_t)ii * NN + jj] = acc;
        ob[(size_t)jj * NN + ii] = acc;
    }
}

// ---------------------------------------------------------------------------
// Kernel 2: in-place row softmax over the last axis.  One block per (b, i).
// ---------------------------------------------------------------------------
__global__ __launch_bounds__(256)
void adj_softmax_kernel(float* __restrict__ out)
{
    float* __restrict__ p = out + (size_t)blockIdx.x * NN;
    const int tid = threadIdx.x;

    float v0 = p[tid];
    float v1 = p[tid + 256];

    // block max
    float m = fmaxf(v0, v1);
    #pragma unroll
    for (int o = 16; o; o >>= 1) m = fmaxf(m, __shfl_xor_sync(0xFFFFFFFFu, m, o));
    __shared__ float redm[8];
    if ((tid & 31) == 0) redm[tid >> 5] = m;
    __syncthreads();
    float M = redm[0];
    #pragma unroll
    for (int k = 1; k < 8; ++k) M = fmaxf(M, redm[k]);

    float e0 = __expf(v0 - M);
    float e1 = __expf(v1 - M);

    // block sum
    float s = e0 + e1;
    #pragma unroll
    for (int o = 16; o; o >>= 1) s += __shfl_xor_sync(0xFFFFFFFFu, s, o);
    __shared__ float reds[8];
    if ((tid & 31) == 0) reds[tid >> 5] = s;
    __syncthreads();
    float S = reds[0];
    #pragma unroll
    for (int k = 1; k < 8; ++k) S += reds[k];

    float inv = __fdividef(1.0f, S);
    p[tid]       = e0 * inv;
    p[tid + 256] = e1 * inv;
}

extern "C" void kernel_launch(void* const* d_in, const int* in_sizes, int n_in,
                              void* d_out, int out_size)
{
    const float* v  = (const float*)d_in[0];
    const float* W1 = (const float*)d_in[1];
    const float* b1 = (const float*)d_in[2];
    const float* W2 = (const float*)d_in[3];
    const float* b2 = (const float*)d_in[4];
    const float* W3 = (const float*)d_in[5];
    const float* b3 = (const float*)d_in[6];
    float* out = (float*)d_out;

    dim3 grid1(NPAIRS, NB);
    adj_logits_kernel<<<grid1, 128>>>(v, W1, b1, W2, b2, W3, b3, out);
    adj_softmax_kernel<<<NB * NN, 256>>>(out);
}

// round 3
// speedup vs baseline: 3.8722x; 3.8722x over previous
#include <cuda_runtime.h>
#include <stdint.h>

#define NB 4
#define NN 512
#define DD 128
#define H1C 64
#define H2C 32
#define NT 8                       // 512/64 tiles
#define NPAIRS (NT * (NT + 1) / 2) // 36

// ---- dynamic shared memory layout (bytes) ----
#define OFF_VI   0                 // 64 x 132 fp32 (padded)
#define OFF_VJ   33792
#define OFF_W1F  67584             // 16 ks x 32 lane x 16 u32 (tf32 frags)
#define OFF_W2F  100352            // 8 ks x 32 lane x 8 u32
#define OFF_H1S  108544            // 8 warps x 16 x 68 u32
#define SMEM_TOTAL 143360

static __device__ __forceinline__ uint32_t cvt_tf32(float x) {
    uint32_t u;
    asm("cvt.rna.tf32.f32 %0, %1;" : "=r"(u) : "f"(x));
    return u;
}
static __device__ __forceinline__ void mma_tf32(float* c,
        uint32_t a0, uint32_t a1, uint32_t a2, uint32_t a3,
        uint32_t b0, uint32_t b1) {
    asm volatile(
        "mma.sync.aligned.m16n8k8.row.col.f32.tf32.tf32.f32 "
        "{%0,%1,%2,%3}, {%4,%5,%6,%7}, {%8,%9}, {%0,%1,%2,%3};"
        : "+f"(c[0]), "+f"(c[1]), "+f"(c[2]), "+f"(c[3])
        : "r"(a0), "r"(a1), "r"(a2), "r"(a3), "r"(b0), "r"(b1));
}
static __device__ __forceinline__ float leaky(float x) { return fmaxf(x, 0.1f * x); }

// ---------------------------------------------------------------------------
// Symmetric HMMA logits kernel. CTA = (batch, tile-pair ti<=tj of 64x64).
// 8 warps; warp w owns i-rows ti*64 + w*8 .. +7; m-tiles of 16 j each.
// ---------------------------------------------------------------------------
__global__ __launch_bounds__(256, 1)
void adj_hmma_kernel(const float* __restrict__ v,
                     const float* __restrict__ W1, const float* __restrict__ b1,
                     const float* __restrict__ W2, const float* __restrict__ b2,
                     const float* __restrict__ W3, const float* __restrict__ b3,
                     float* __restrict__ out)
{
    extern __shared__ char sm[];
    float*    VI  = (float*)(sm + OFF_VI);
    float*    VJ  = (float*)(sm + OFF_VJ);
    uint32_t* W1F = (uint32_t*)(sm + OFF_W1F);
    uint32_t* W2F = (uint32_t*)(sm + OFF_W2F);

    const int tid  = threadIdx.x;
    const int wid  = tid >> 5;
    const int lane = tid & 31;
    const int g    = lane >> 2;   // groupID (row within fragment)
    const int t    = lane & 3;    // threadID_in_group (col base)
    const int b    = blockIdx.y;

    // decode (ti, tj), ti <= tj
    int rem = blockIdx.x;
    int ti = 0;
    while (rem >= NT - ti) { rem -= NT - ti; ti++; }
    const int tj = ti + rem;

    // ---- load v tiles (64 x 128 each, rows padded to 132) ----
    const float* vb = v + (size_t)b * NN * DD;
    for (int e = tid; e < 64 * 32; e += 256) {
        int r = e >> 5, c = e & 31;
        ((float4*)(VI + r * 132))[c] = ((const float4*)(vb + (size_t)(ti * 64 + r) * DD))[c];
        ((float4*)(VJ + r * 132))[c] = ((const float4*)(vb + (size_t)(tj * 64 + r) * DD))[c];
    }
    // ---- W1 fragments: b0/b1 per (ks, lane, nstep) pre-converted to tf32 ----
    for (int idx = tid; idx < 16 * 32 * 16; idx += 256) {
        int ks = idx >> 9, ln = (idx >> 4) & 31, rm = idx & 15;
        int n = rm >> 1, e = rm & 1;
        int o = (ln >> 2) + 8 * n;
        int d = (ln & 3) + 4 * e + 8 * ks;
        W1F[idx] = cvt_tf32(W1[o * DD + d]);
    }
    // ---- W2 fragments ----
    for (int idx = tid; idx < 8 * 32 * 8; idx += 256) {
        int ks = idx >> 8, ln = (idx >> 3) & 31, rm = idx & 7;
        int n = rm >> 1, e = rm & 1;
        int o = (ln >> 2) + 8 * n;
        int k = (ln & 3) + 4 * e + 8 * ks;
        W2F[idx] = cvt_tf32(W2[o * H1C + k]);
    }
    // per-thread bias / w3 values at this thread's fragment columns
    float b1v[16], b2v[8], w3v[8];
    #pragma unroll
    for (int n = 0; n < 8; ++n) {
        b1v[2 * n]     = b1[8 * n + 2 * t];
        b1v[2 * n + 1] = b1[8 * n + 2 * t + 1];
    }
    #pragma unroll
    for (int n = 0; n < 4; ++n) {
        b2v[2 * n]     = b2[8 * n + 2 * t];
        b2v[2 * n + 1] = b2[8 * n + 2 * t + 1];
        w3v[2 * n]     = W3[8 * n + 2 * t];
        w3v[2 * n + 1] = W3[8 * n + 2 * t + 1];
    }
    const float bias3 = b3[0];
    __syncthreads();

    uint32_t* h1w = (uint32_t*)(sm + OFF_H1S) + wid * (16 * 68);
    float* ob = out + (size_t)b * NN * NN;

    for (int ii = 0; ii < 8; ++ii) {
        const int il = wid * 8 + ii;          // local i row
        const int ig = ti * 64 + il;          // global i
        const float* vi_row = VI + il * 132;

        for (int jm = 0; jm < 4; ++jm) {
            const float* vj0 = VJ + (jm * 16 + g) * 132;
            const float* vj1 = vj0 + 8 * 132;

            // ---- GEMM1: h1[16j x 64] = |vi - vj| @ W1^T,  K = 128 ----
            float c1[8][4];
            #pragma unroll
            for (int n = 0; n < 8; ++n)
                c1[n][0] = c1[n][1] = c1[n][2] = c1[n][3] = 0.0f;

            #pragma unroll
            for (int ks = 0; ks < 16; ++ks) {
                const int d0 = 8 * ks + t, d1 = d0 + 4;
                float x0 = vi_row[d0], x1 = vi_row[d1];
                uint32_t a0 = cvt_tf32(fabsf(x0 - vj0[d0]));
                uint32_t a1 = cvt_tf32(fabsf(x0 - vj1[d0]));
                uint32_t a2 = cvt_tf32(fabsf(x1 - vj0[d1]));
                uint32_t a3 = cvt_tf32(fabsf(x1 - vj1[d1]));
                const uint32_t* wq = W1F + ks * 512 + lane * 16;
                #pragma unroll
                for (int n = 0; n < 8; ++n)
                    mma_tf32(c1[n], a0, a1, a2, a3, wq[2 * n], wq[2 * n + 1]);
            }

            // ---- bias + leaky, re-fragment via per-warp SMEM scratch ----
            __syncwarp();
            #pragma unroll
            for (int n = 0; n < 8; ++n) {
                h1w[g * 68 + 8 * n + 2 * t]           = cvt_tf32(leaky(c1[n][0] + b1v[2 * n]));
                h1w[g * 68 + 8 * n + 2 * t + 1]       = cvt_tf32(leaky(c1[n][1] + b1v[2 * n + 1]));
                h1w[(g + 8) * 68 + 8 * n + 2 * t]     = cvt_tf32(leaky(c1[n][2] + b1v[2 * n]));
                h1w[(g + 8) * 68 + 8 * n + 2 * t + 1] = cvt_tf32(leaky(c1[n][3] + b1v[2 * n + 1]));
            }
            __syncwarp();

            // ---- GEMM2: h2[16j x 32] = h1 @ W2^T,  K = 64 ----
            float c2[4][4];
            #pragma unroll
            for (int n = 0; n < 4; ++n)
                c2[n][0] = c2[n][1] = c2[n][2] = c2[n][3] = 0.0f;

            #pragma unroll
            for (int ks = 0; ks < 8; ++ks) {
                uint32_t a0 = h1w[g * 68 + 8 * ks + t];
                uint32_t a1 = h1w[(g + 8) * 68 + 8 * ks + t];
                uint32_t a2 = h1w[g * 68 + 8 * ks + t + 4];
                uint32_t a3 = h1w[(g + 8) * 68 + 8 * ks + t + 4];
                const uint32_t* wq = W2F + ks * 256 + lane * 8;
                #pragma unroll
                for (int n = 0; n < 4; ++n)
                    mma_tf32(c2[n], a0, a1, a2, a3, wq[2 * n], wq[2 * n + 1]);
            }

            // ---- layer 3: logit = w3 . leaky(h2 + b2) + b3 ----
            float p0 = 0.0f, p1 = 0.0f;
            #pragma unroll
            for (int n = 0; n < 4; ++n) {
                p0 += leaky(c2[n][0] + b2v[2 * n]) * w3v[2 * n];
                p0 += leaky(c2[n][1] + b2v[2 * n + 1]) * w3v[2 * n + 1];
                p1 += leaky(c2[n][2] + b2v[2 * n]) * w3v[2 * n];
                p1 += leaky(c2[n][3] + b2v[2 * n + 1]) * w3v[2 * n + 1];
            }
            // reduce across the 4 threads of each row-group (quads aligned)
            p0 += __shfl_xor_sync(0xFFFFFFFFu, p0, 1);
            p0 += __shfl_xor_sync(0xFFFFFFFFu, p0, 2);
            p1 += __shfl_xor_sync(0xFFFFFFFFu, p1, 1);
            p1 += __shfl_xor_sync(0xFFFFFFFFu, p1, 2);

            if (t == 0) {
                const int jg = tj * 64 + jm * 16 + g;
                float v0 = p0 + bias3, v1 = p1 + bias3;
                ob[(size_t)ig * NN + jg]     = v0;
                ob[(size_t)ig * NN + jg + 8] = v1;
                if (ti != tj) {   // mirror (logits exactly symmetric)
                    ob[(size_t)jg * NN + ig]       = v0;
                    ob[(size_t)(jg + 8) * NN + ig] = v1;
                }
            }
        }
    }
}

// ---------------------------------------------------------------------------
// Row softmax over last axis. One block per (b, i).
// ---------------------------------------------------------------------------
__global__ __launch_bounds__(256)
void adj_softmax_kernel(float* __restrict__ out)
{
    float* __restrict__ p = out + (size_t)blockIdx.x * NN;
    const int tid = threadIdx.x;

    float v0 = p[tid];
    float v1 = p[tid + 256];

    float m = fmaxf(v0, v1);
    #pragma unroll
    for (int o = 16; o; o >>= 1) m = fmaxf(m, __shfl_xor_sync(0xFFFFFFFFu, m, o));
    __shared__ float redm[8];
    if ((tid & 31) == 0) redm[tid >> 5] = m;
    __syncthreads();
    float M = redm[0];
    #pragma unroll
    for (int k = 1; k < 8; ++k) M = fmaxf(M, redm[k]);

    float e0 = __expf(v0 - M);
    float e1 = __expf(v1 - M);

    float s = e0 + e1;
    #pragma unroll
    for (int o = 16; o; o >>= 1) s += __shfl_xor_sync(0xFFFFFFFFu, s, o);
    __shared__ float reds[8];
    if ((tid & 31) == 0) reds[tid >> 5] = s;
    __syncthreads();
    float S = reds[0];
    #pragma unroll
    for (int k = 1; k < 8; ++k) S += reds[k];

    float inv = __fdividef(1.0f, S);
    p[tid]       = e0 * inv;
    p[tid + 256] = e1 * inv;
}

extern "C" void kernel_launch(void* const* d_in, const int* in_sizes, int n_in,
                              void* d_out, int out_size)
{
    const float* v  = (const float*)d_in[0];
    const float* W1 = (const float*)d_in[1];
    const float* b1 = (const float*)d_in[2];
    const float* W2 = (const float*)d_in[3];
    const float* b2 = (const float*)d_in[4];
    const float* W3 = (const float*)d_in[5];
    const float* b3 = (const float*)d_in[6];
    float* out = (float*)d_out;

    cudaFuncSetAttribute(adj_hmma_kernel,
                         cudaFuncAttributeMaxDynamicSharedMemorySize, SMEM_TOTAL);

    dim3 grid(NPAIRS, NB);   // (36, 4) — one wave of 144 CTAs
    adj_hmma_kernel<<<grid, 256, SMEM_TOTAL>>>(v, W1, b1, W2, b2, W3, b3, out);
    adj_softmax_kernel<<<NB * NN, 256>>>(out);
}

// round 4
// speedup vs baseline: 3.8972x; 1.0065x over previous
#include <cuda_runtime.h>
#include <stdint.h>

#define NB 4
#define NN 512
#define DD 128
#define H1C 64
#define H2C 32
#define NT 8                       // 512/64 tiles
#define NPAIRS (NT * (NT + 1) / 2) // 36
#define THREADS 512

// ---- dynamic shared memory layout (bytes) ----
#define OFF_VI   0                 // 64 x 132 fp32 (padded)
#define OFF_VJ   33792
#define OFF_W1F  67584             // 16 ks x 32 lane x 16 u32 (tf32 frags)
#define OFF_W2F  100352            // 8 ks x 32 lane x 8 u32
#define OFF_B1S  108544            // 64 floats
#define OFF_H1S  108800            // 16 warps x 16 x 68 u32
#define SMEM_TOTAL (108800 + 16 * 16 * 68 * 4)   // 178432

static __device__ __forceinline__ uint32_t cvt_tf32(float x) {
    uint32_t u;
    asm("cvt.rna.tf32.f32 %0, %1;" : "=r"(u) : "f"(x));
    return u;
}
static __device__ __forceinline__ void mma_tf32(float* c,
        uint32_t a0, uint32_t a1, uint32_t a2, uint32_t a3,
        uint32_t b0, uint32_t b1) {
    asm volatile(
        "mma.sync.aligned.m16n8k8.row.col.f32.tf32.tf32.f32 "
        "{%0,%1,%2,%3}, {%4,%5,%6,%7}, {%8,%9}, {%0,%1,%2,%3};"
        : "+f"(c[0]), "+f"(c[1]), "+f"(c[2]), "+f"(c[3])
        : "r"(a0), "r"(a1), "r"(a2), "r"(a3), "r"(b0), "r"(b1));
}
static __device__ __forceinline__ float leaky(float x) { return fmaxf(x, 0.1f * x); }

// ---------------------------------------------------------------------------
// Symmetric HMMA logits kernel. CTA = (batch, tile-pair ti<=tj of 64x64).
// 16 warps (4/SMSP); warp w owns i-rows ti*64 + w*4 .. +3; m-tiles of 16 j.
// ---------------------------------------------------------------------------
__global__ __launch_bounds__(THREADS, 1)
void adj_hmma_kernel(const float* __restrict__ v,
                     const float* __restrict__ W1, const float* __restrict__ b1,
                     const float* __restrict__ W2, const float* __restrict__ b2,
                     const float* __restrict__ W3, const float* __restrict__ b3,
                     float* __restrict__ out)
{
    extern __shared__ char sm[];
    float*    VI  = (float*)(sm + OFF_VI);
    float*    VJ  = (float*)(sm + OFF_VJ);
    uint32_t* W1F = (uint32_t*)(sm + OFF_W1F);
    uint32_t* W2F = (uint32_t*)(sm + OFF_W2F);
    float*    B1S = (float*)(sm + OFF_B1S);

    const int tid  = threadIdx.x;
    const int wid  = tid >> 5;
    const int lane = tid & 31;
    const int g    = lane >> 2;   // groupID (row within fragment)
    const int t    = lane & 3;    // threadID_in_group (col base)
    const int b    = blockIdx.y;

    // decode (ti, tj), ti <= tj
    int rem = blockIdx.x;
    int ti = 0;
    while (rem >= NT - ti) { rem -= NT - ti; ti++; }
    const int tj = ti + rem;

    // ---- load v tiles (64 x 128 each, rows padded to 132) ----
    const float* vb = v + (size_t)b * NN * DD;
    for (int e = tid; e < 64 * 32; e += THREADS) {
        int r = e >> 5, c = e & 31;
        ((float4*)(VI + r * 132))[c] = ((const float4*)(vb + (size_t)(ti * 64 + r) * DD))[c];
        ((float4*)(VJ + r * 132))[c] = ((const float4*)(vb + (size_t)(tj * 64 + r) * DD))[c];
    }
    // ---- W1 fragments: b0/b1 per (ks, lane, nstep) pre-converted to tf32 ----
    for (int idx = tid; idx < 16 * 32 * 16; idx += THREADS) {
        int ks = idx >> 9, ln = (idx >> 4) & 31, rm = idx & 15;
        int n = rm >> 1, e = rm & 1;
        int o = (ln >> 2) + 8 * n;
        int d = (ln & 3) + 4 * e + 8 * ks;
        W1F[idx] = cvt_tf32(W1[o * DD + d]);
    }
    // ---- W2 fragments ----
    for (int idx = tid; idx < 8 * 32 * 8; idx += THREADS) {
        int ks = idx >> 8, ln = (idx >> 3) & 31, rm = idx & 7;
        int n = rm >> 1, e = rm & 1;
        int o = (ln >> 2) + 8 * n;
        int k = (ln & 3) + 4 * e + 8 * ks;
        W2F[idx] = cvt_tf32(W2[o * H1C + k]);
    }
    if (tid < H1C) B1S[tid] = b1[tid];
    // per-thread bias / w3 values at this thread's fragment columns
    float b2v[8], w3v[8];
    #pragma unroll
    for (int n = 0; n < 4; ++n) {
        b2v[2 * n]     = b2[8 * n + 2 * t];
        b2v[2 * n + 1] = b2[8 * n + 2 * t + 1];
        w3v[2 * n]     = W3[8 * n + 2 * t];
        w3v[2 * n + 1] = W3[8 * n + 2 * t + 1];
    }
    const float bias3 = b3[0];
    __syncthreads();

    uint32_t* h1w = (uint32_t*)(sm + OFF_H1S) + wid * (16 * 68);
    float* ob = out + (size_t)b * NN * NN;

    for (int ii = 0; ii < 4; ++ii) {
        const int il = wid * 4 + ii;          // local i row
        const int ig = ti * 64 + il;          // global i
        const float* vi_row = VI + il * 132;

        // hoist this i-row's values at this thread's k-columns into registers
        float vix[16], viy[16];
        #pragma unroll
        for (int ks = 0; ks < 16; ++ks) {
            vix[ks] = vi_row[8 * ks + t];
            viy[ks] = vi_row[8 * ks + t + 4];
        }

        for (int jm = 0; jm < 4; ++jm) {
            const float* vj0 = VJ + (jm * 16 + g) * 132;
            const float* vj1 = vj0 + 8 * 132;

            // ---- GEMM1: h1[16j x 64] = |vi - vj| @ W1^T,  K = 128 ----
            float c1[8][4];
            #pragma unroll
            for (int n = 0; n < 8; ++n)
                c1[n][0] = c1[n][1] = c1[n][2] = c1[n][3] = 0.0f;

            #pragma unroll
            for (int ks = 0; ks < 16; ++ks) {
                const int d0 = 8 * ks + t, d1 = d0 + 4;
                uint32_t a0 = cvt_tf32(fabsf(vix[ks] - vj0[d0]));
                uint32_t a1 = cvt_tf32(fabsf(vix[ks] - vj1[d0]));
                uint32_t a2 = cvt_tf32(fabsf(viy[ks] - vj0[d1]));
                uint32_t a3 = cvt_tf32(fabsf(viy[ks] - vj1[d1]));
                const uint32_t* wq = W1F + ks * 512 + lane * 16;
                #pragma unroll
                for (int n = 0; n < 8; ++n)
                    mma_tf32(c1[n], a0, a1, a2, a3, wq[2 * n], wq[2 * n + 1]);
            }

            // ---- bias + leaky, re-fragment via per-warp SMEM scratch ----
            __syncwarp();
            #pragma unroll
            for (int n = 0; n < 8; ++n) {
                float bb0 = B1S[8 * n + 2 * t];
                float bb1 = B1S[8 * n + 2 * t + 1];
                h1w[g * 68 + 8 * n + 2 * t]           = cvt_tf32(leaky(c1[n][0] + bb0));
                h1w[g * 68 + 8 * n + 2 * t + 1]       = cvt_tf32(leaky(c1[n][1] + bb1));
                h1w[(g + 8) * 68 + 8 * n + 2 * t]     = cvt_tf32(leaky(c1[n][2] + bb0));
                h1w[(g + 8) * 68 + 8 * n + 2 * t + 1] = cvt_tf32(leaky(c1[n][3] + bb1));
            }
            __syncwarp();

            // ---- GEMM2: h2[16j x 32] = h1 @ W2^T,  K = 64 ----
            float c2[4][4];
            #pragma unroll
            for (int n = 0; n < 4; ++n)
                c2[n][0] = c2[n][1] = c2[n][2] = c2[n][3] = 0.0f;

            #pragma unroll
            for (int ks = 0; ks < 8; ++ks) {
                uint32_t a0 = h1w[g * 68 + 8 * ks + t];
                uint32_t a1 = h1w[(g + 8) * 68 + 8 * ks + t];
                uint32_t a2 = h1w[g * 68 + 8 * ks + t + 4];
                uint32_t a3 = h1w[(g + 8) * 68 + 8 * ks + t + 4];
                const uint32_t* wq = W2F + ks * 256 + lane * 8;
                #pragma unroll
                for (int n = 0; n < 4; ++n)
                    mma_tf32(c2[n], a0, a1, a2, a3, wq[2 * n], wq[2 * n + 1]);
            }

            // ---- layer 3: logit = w3 . leaky(h2 + b2) + b3 ----
            float p0 = 0.0f, p1 = 0.0f;
            #pragma unroll
            for (int n = 0; n < 4; ++n) {
                p0 += leaky(c2[n][0] + b2v[2 * n]) * w3v[2 * n];
                p0 += leaky(c2[n][1] + b2v[2 * n + 1]) * w3v[2 * n + 1];
                p1 += leaky(c2[n][2] + b2v[2 * n]) * w3v[2 * n];
                p1 += leaky(c2[n][3] + b2v[2 * n + 1]) * w3v[2 * n + 1];
            }
            // reduce across the 4 threads of each row-group (quads aligned)
            p0 += __shfl_xor_sync(0xFFFFFFFFu, p0, 1);
            p0 += __shfl_xor_sync(0xFFFFFFFFu, p0, 2);
            p1 += __shfl_xor_sync(0xFFFFFFFFu, p1, 1);
            p1 += __shfl_xor_sync(0xFFFFFFFFu, p1, 2);

            if (t == 0) {
                const int jg = tj * 64 + jm * 16 + g;
                float v0 = p0 + bias3, v1 = p1 + bias3;
                ob[(size_t)ig * NN + jg]     = v0;
                ob[(size_t)ig * NN + jg + 8] = v1;
                if (ti != tj) {   // mirror (logits exactly symmetric)
                    ob[(size_t)jg * NN + ig]       = v0;
                    ob[(size_t)(jg + 8) * NN + ig] = v1;
                }
            }
        }
    }
}

// ---------------------------------------------------------------------------
// Row softmax over last axis. One block per (b, i).
// ---------------------------------------------------------------------------
__global__ __launch_bounds__(256)
void adj_softmax_kernel(float* __restrict__ out)
{
    float* __restrict__ p = out + (size_t)blockIdx.x * NN;
    const int tid = threadIdx.x;

    float v0 = p[tid];
    float v1 = p[tid + 256];

    float m = fmaxf(v0, v1);
    #pragma unroll
    for (int o = 16; o; o >>= 1) m = fmaxf(m, __shfl_xor_sync(0xFFFFFFFFu, m, o));
    __shared__ float redm[8];
    if ((tid & 31) == 0) redm[tid >> 5] = m;
    __syncthreads();
    float M = redm[0];
    #pragma unroll
    for (int k = 1; k < 8; ++k) M = fmaxf(M, redm[k]);

    float e0 = __expf(v0 - M);
    float e1 = __expf(v1 - M);

    float s = e0 + e1;
    #pragma unroll
    for (int o = 16; o; o >>= 1) s += __shfl_xor_sync(0xFFFFFFFFu, s, o);
    __shared__ float reds[8];
    if ((tid & 31) == 0) reds[tid >> 5] = s;
    __syncthreads();
    float S = reds[0];
    #pragma unroll
    for (int k = 1; k < 8; ++k) S += reds[k];

    float inv = __fdividef(1.0f, S);
    p[tid]       = e0 * inv;
    p[tid + 256] = e1 * inv;
}

extern "C" void kernel_launch(void* const* d_in, const int* in_sizes, int n_in,
                              void* d_out, int out_size)
{
    const float* v  = (const float*)d_in[0];
    const float* W1 = (const float*)d_in[1];
    const float* b1 = (const float*)d_in[2];
    const float* W2 = (const float*)d_in[3];
    const float* b2 = (const float*)d_in[4];
    const float* W3 = (const float*)d_in[5];
    const float* b3 = (const float*)d_in[6];
    float* out = (float*)d_out;

    cudaFuncSetAttribute(adj_hmma_kernel,
                         cudaFuncAttributeMaxDynamicSharedMemorySize, SMEM_TOTAL);

    dim3 grid(NPAIRS, NB);   // (36, 4) — one wave of 144 CTAs
    adj_hmma_kernel<<<grid, THREADS, SMEM_TOTAL>>>(v, W1, b1, W2, b2, W3, b3, out);
    adj_softmax_kernel<<<NB * NN, 256>>>(out);
}

// round 5
// speedup vs baseline: 6.3285x; 1.6239x over previous
#include <cuda_runtime.h>
#include <stdint.h>

#define NB 4
#define NN 512
#define DD 128
#define H1C 64
#define H2C 32
#define NT 8                       // 512/64 tiles
#define NPAIRS (NT * (NT + 1) / 2) // 36
#define THREADS 512

// ---- dynamic shared memory layout (bytes) ----
#define OFF_VI   0                 // 64 x 132 fp32 (padded)
#define OFF_VJ   33792             // 64 x 132 fp32
#define OFF_W1F  67584             // 8 ks x 32 lane x 16 u32 (half2 frags) = 16384
#define OFF_W2F  83968             // 4 ks x 32 lane x 8 u32 = 4096
#define OFF_H1S  88064             // 16 warps x 16 rows x 36 u32 = 36864
#define SMEM_TOTAL 124928

static __device__ __forceinline__ uint32_t packh2(float lo, float hi) {
    uint32_t u;
    asm("cvt.rn.f16x2.f32 %0, %1, %2;" : "=r"(u) : "f"(hi), "f"(lo));
    return u;
}
static __device__ __forceinline__ void mma_f16(float* c,
        uint32_t a0, uint32_t a1, uint32_t a2, uint32_t a3,
        uint32_t b0, uint32_t b1) {
    asm volatile(
        "mma.sync.aligned.m16n8k16.row.col.f32.f16.f16.f32 "
        "{%0,%1,%2,%3}, {%4,%5,%6,%7}, {%8,%9}, {%0,%1,%2,%3};"
        : "+f"(c[0]), "+f"(c[1]), "+f"(c[2]), "+f"(c[3])
        : "r"(a0), "r"(a1), "r"(a2), "r"(a3), "r"(b0), "r"(b1));
}
static __device__ __forceinline__ float leaky(float x) { return fmaxf(x, 0.1f * x); }

// no-op kernel: shifts launch indices so ncu -s5 captures the hmma kernel
__global__ void adj_dummy_kernel() {}

// ---------------------------------------------------------------------------
// Symmetric fp16-HMMA logits kernel. CTA = (batch, tile-pair ti<=tj, 64x64).
// 16 warps; warp w owns i-rows ti*64 + w*4 .. +3; 4 m-tiles of 16 j each.
// ---------------------------------------------------------------------------
__global__ __launch_bounds__(THREADS, 1)
void adj_hmma_kernel(const float* __restrict__ v,
                     const float* __restrict__ W1, const float* __restrict__ b1,
                     const float* __restrict__ W2, const float* __restrict__ b2,
                     const float* __restrict__ W3, const float* __restrict__ b3,
                     float* __restrict__ out)
{
    extern __shared__ char sm[];
    float*    VI  = (float*)(sm + OFF_VI);
    float*    VJ  = (float*)(sm + OFF_VJ);
    uint32_t* W1F = (uint32_t*)(sm + OFF_W1F);
    uint32_t* W2F = (uint32_t*)(sm + OFF_W2F);

    const int tid  = threadIdx.x;
    const int wid  = tid >> 5;
    const int lane = tid & 31;
    const int g    = lane >> 2;   // groupID (row within fragment)
    const int t    = lane & 3;    // threadID_in_group
    const int b    = blockIdx.y;

    // decode (ti, tj), ti <= tj
    int rem = blockIdx.x;
    int ti = 0;
    while (rem >= NT - ti) { rem -= NT - ti; ti++; }
    const int tj = ti + rem;

    // ---- load v tiles (64 x 128 each, rows padded to 132 floats) ----
    const float* vb = v + (size_t)b * NN * DD;
    for (int e = tid; e < 64 * 32; e += THREADS) {
        int r = e >> 5, c = e & 31;
        ((float4*)(VI + r * 132))[c] = ((const float4*)(vb + (size_t)(ti * 64 + r) * DD))[c];
        ((float4*)(VJ + r * 132))[c] = ((const float4*)(vb + (size_t)(tj * 64 + r) * DD))[c];
    }
    // ---- W1 half2 fragments: [ks(8)][lane(32)][n(8)x{b0,b1}] ----
    for (int idx = tid; idx < 8 * 32 * 16; idx += THREADS) {
        int ks = idx >> 9, ln = (idx >> 4) & 31, rm = idx & 15;
        int n = rm >> 1, e = rm & 1;
        int o  = (ln >> 2) + 8 * n;
        int kb = 16 * ks + 2 * (ln & 3) + 8 * e;
        W1F[idx] = packh2(W1[o * DD + kb], W1[o * DD + kb + 1]);
    }
    // ---- W2 half2 fragments: [ks(4)][lane(32)][n(4)x{b0,b1}] ----
    for (int idx = tid; idx < 4 * 32 * 8; idx += THREADS) {
        int ks = idx >> 8, ln = (idx >> 3) & 31, rm = idx & 7;
        int n = rm >> 1, e = rm & 1;
        int o  = (ln >> 2) + 8 * n;
        int kb = 16 * ks + 2 * (ln & 3) + 8 * e;
        W2F[idx] = packh2(W2[o * H1C + kb], W2[o * H1C + kb + 1]);
    }
    // per-thread bias / w3 values at this thread's fragment columns
    float b1r[16], b2v[8], w3v[8];
    #pragma unroll
    for (int n = 0; n < 8; ++n) {
        b1r[2 * n]     = b1[8 * n + 2 * t];
        b1r[2 * n + 1] = b1[8 * n + 2 * t + 1];
    }
    #pragma unroll
    for (int n = 0; n < 4; ++n) {
        b2v[2 * n]     = b2[8 * n + 2 * t];
        b2v[2 * n + 1] = b2[8 * n + 2 * t + 1];
        w3v[2 * n]     = W3[8 * n + 2 * t];
        w3v[2 * n + 1] = W3[8 * n + 2 * t + 1];
    }
    const float bias3 = b3[0];
    __syncthreads();

    uint32_t* h1w = (uint32_t*)(sm + OFF_H1S) + wid * (16 * 36);
    float* ob = out + (size_t)b * NN * NN;

    for (int ii = 0; ii < 4; ++ii) {
        const int il = wid * 4 + ii;          // local i row
        const int ig = ti * 64 + il;          // global i
        const float2* vi2 = (const float2*)(VI + il * 132);

        // hoist this i-row's values at this thread's k-positions
        float2 vilo[8], vihi[8];
        #pragma unroll
        for (int ks = 0; ks < 8; ++ks) {
            vilo[ks] = vi2[8 * ks + t];       // k = 16ks+2t, +1
            vihi[ks] = vi2[8 * ks + t + 4];   // k = 16ks+2t+8, +9
        }

        for (int jm = 0; jm < 4; ++jm) {
            const float2* vj0 = (const float2*)(VJ + (jm * 16 + g) * 132);
            const float2* vj1 = (const float2*)(VJ + (jm * 16 + 8 + g) * 132);

            // ---- GEMM1: h1[16j x 64] = |vi - vj| @ W1^T,  K = 128 ----
            float c1[8][4];
            #pragma unroll
            for (int n = 0; n < 8; ++n) {
                c1[n][0] = b1r[2 * n];     c1[n][1] = b1r[2 * n + 1];
                c1[n][2] = b1r[2 * n];     c1[n][3] = b1r[2 * n + 1];
            }

            #pragma unroll
            for (int ks = 0; ks < 8; ++ks) {
                float2 w0l = vj0[8 * ks + t];
                float2 w0h = vj0[8 * ks + t + 4];
                float2 w1l = vj1[8 * ks + t];
                float2 w1h = vj1[8 * ks + t + 4];
                uint32_t a0 = packh2(fabsf(vilo[ks].x - w0l.x), fabsf(vilo[ks].y - w0l.y));
                uint32_t a1 = packh2(fabsf(vilo[ks].x - w1l.x), fabsf(vilo[ks].y - w1l.y));
                uint32_t a2 = packh2(fabsf(vihi[ks].x - w0h.x), fabsf(vihi[ks].y - w0h.y));
                uint32_t a3 = packh2(fabsf(vihi[ks].x - w1h.x), fabsf(vihi[ks].y - w1h.y));
                const uint32_t* wq = W1F + ks * 512 + lane * 16;
                #pragma unroll
                for (int n = 0; n < 8; ++n)
                    mma_f16(c1[n], a0, a1, a2, a3, wq[2 * n], wq[2 * n + 1]);
            }

            // ---- leaky + pack adjacent channel pairs into per-warp scratch ----
            __syncwarp();
            #pragma unroll
            for (int n = 0; n < 8; ++n) {
                h1w[g * 36 + 4 * n + t]       = packh2(leaky(c1[n][0]), leaky(c1[n][1]));
                h1w[(g + 8) * 36 + 4 * n + t] = packh2(leaky(c1[n][2]), leaky(c1[n][3]));
            }
            __syncwarp();

            // ---- GEMM2: h2[16j x 32] = h1 @ W2^T,  K = 64 ----
            float c2[4][4];
            #pragma unroll
            for (int n = 0; n < 4; ++n) {
                c2[n][0] = b2v[2 * n];     c2[n][1] = b2v[2 * n + 1];
                c2[n][2] = b2v[2 * n];     c2[n][3] = b2v[2 * n + 1];
            }

            #pragma unroll
            for (int ks = 0; ks < 4; ++ks) {
                uint32_t a0 = h1w[g * 36 + 8 * ks + t];
                uint32_t a1 = h1w[(g + 8) * 36 + 8 * ks + t];
                uint32_t a2 = h1w[g * 36 + 8 * ks + t + 4];
                uint32_t a3 = h1w[(g + 8) * 36 + 8 * ks + t + 4];
                const uint32_t* wq = W2F + ks * 256 + lane * 8;
                #pragma unroll
                for (int n = 0; n < 4; ++n)
                    mma_f16(c2[n], a0, a1, a2, a3, wq[2 * n], wq[2 * n + 1]);
            }

            // ---- layer 3: logit = w3 . leaky(h2) + b3 (bias2 already in acc) ----
            float p0 = 0.0f, p1 = 0.0f;
            #pragma unroll
            for (int n = 0; n < 4; ++n) {
                p0 += leaky(c2[n][0]) * w3v[2 * n];
                p0 += leaky(c2[n][1]) * w3v[2 * n + 1];
                p1 += leaky(c2[n][2]) * w3v[2 * n];
                p1 += leaky(c2[n][3]) * w3v[2 * n + 1];
            }
            // reduce across the 4 threads of each row-group
            p0 += __shfl_xor_sync(0xFFFFFFFFu, p0, 1);
            p0 += __shfl_xor_sync(0xFFFFFFFFu, p0, 2);
            p1 += __shfl_xor_sync(0xFFFFFFFFu, p1, 1);
            p1 += __shfl_xor_sync(0xFFFFFFFFu, p1, 2);

            if (t == 0) {
                const int jg = tj * 64 + jm * 16 + g;
                float v0 = p0 + bias3, v1 = p1 + bias3;
                ob[(size_t)ig * NN + jg]     = v0;
                ob[(size_t)ig * NN + jg + 8] = v1;
                if (ti != tj) {   // mirror (logits exactly symmetric)
                    ob[(size_t)jg * NN + ig]       = v0;
                    ob[(size_t)(jg + 8) * NN + ig] = v1;
                }
            }
        }
    }
}

// ---------------------------------------------------------------------------
// Row softmax over last axis. One block per (b, i).
// ---------------------------------------------------------------------------
__global__ __launch_bounds__(256)
void adj_softmax_kernel(float* __restrict__ out)
{
    float* __restrict__ p = out + (size_t)blockIdx.x * NN;
    const int tid = threadIdx.x;

    float v0 = p[tid];
    float v1 = p[tid + 256];

    float m = fmaxf(v0, v1);
    #pragma unroll
    for (int o = 16; o; o >>= 1) m = fmaxf(m, __shfl_xor_sync(0xFFFFFFFFu, m, o));
    __shared__ float redm[8];
    if ((tid & 31) == 0) redm[tid >> 5] = m;
    __syncthreads();
    float M = redm[0];
    #pragma unroll
    for (int k = 1; k < 8; ++k) M = fmaxf(M, redm[k]);

    float e0 = __expf(v0 - M);
    float e1 = __expf(v1 - M);

    float s = e0 + e1;
    #pragma unroll
    for (int o = 16; o; o >>= 1) s += __shfl_xor_sync(0xFFFFFFFFu, s, o);
    __shared__ float reds[8];
    if ((tid & 31) == 0) reds[tid >> 5] = s;
    __syncthreads();
    float S = reds[0];
    #pragma unroll
    for (int k = 1; k < 8; ++k) S += reds[k];

    float inv = __fdividef(1.0f, S);
    p[tid]       = e0 * inv;
    p[tid + 256] = e1 * inv;
}

extern "C" void kernel_launch(void* const* d_in, const int* in_sizes, int n_in,
                              void* d_out, int out_size)
{
    const float* v  = (const float*)d_in[0];
    const float* W1 = (const float*)d_in[1];
    const float* b1 = (const float*)d_in[2];
    const float* W2 = (const float*)d_in[3];
    const float* b2 = (const float*)d_in[4];
    const float* W3 = (const float*)d_in[5];
    const float* b3 = (const float*)d_in[6];
    float* out = (float*)d_out;

    cudaFuncSetAttribute(adj_hmma_kernel,
                         cudaFuncAttributeMaxDynamicSharedMemorySize, SMEM_TOTAL);

    // launch order (dummy, hmma, softmax, dummy): period 4 puts ncu's
    // skip-5 capture (index 5 == 1 mod 4) on the hmma kernel.
    adj_dummy_kernel<<<1, 32>>>();
    dim3 grid(NPAIRS, NB);   // (36, 4) — one wave of 144 CTAs
    adj_hmma_kernel<<<grid, THREADS, SMEM_TOTAL>>>(v, W1, b1, W2, b2, W3, b3, out);
    adj_softmax_kernel<<<NB * NN, 256>>>(out);
    adj_dummy_kernel<<<1, 32>>>();
}

// round 6
// speedup vs baseline: 7.1768x; 1.1340x over previous
#include <cuda_runtime.h>
#include <stdint.h>

#define NB 4
#define NN 512
#define DD 128
#define H1C 64
#define H2C 32
#define NT 8                       // 512/64 tiles
#define NPAIRS (NT * (NT + 1) / 2) // 36
#define THREADS 512

// ---- dynamic shared memory layout (bytes) ----
// VIh/VJh: 64 rows x 68 u32 (64 half2 data + 4 pad) each
#define OFF_VIH  0                 // 64*68*4 = 17408
#define OFF_VJH  17408             // 17408
#define OFF_W1F  34816             // 8 ks x 32 lane x 16 u32 = 16384
#define OFF_W2F  51200             // 4 ks x 32 lane x 8 u32 = 4096
#define OFF_H1S  55296             // 16 warps x 16 rows x 36 u32 = 36864
#define SMEM_TOTAL 92160

static __device__ __forceinline__ uint32_t packh2(float lo, float hi) {
    uint32_t u;
    asm("cvt.rn.f16x2.f32 %0, %1, %2;" : "=r"(u) : "f"(hi), "f"(lo));
    return u;
}
static __device__ __forceinline__ uint32_t habs2_sub(uint32_t a, uint32_t b) {
    uint32_t d;
    asm("sub.f16x2 %0, %1, %2;" : "=r"(d) : "r"(a), "r"(b));
    return d & 0x7FFF7FFFu;
}
static __device__ __forceinline__ void mma_f16(float* c,
        uint32_t a0, uint32_t a1, uint32_t a2, uint32_t a3,
        uint32_t b0, uint32_t b1) {
    asm volatile(
        "mma.sync.aligned.m16n8k16.row.col.f32.f16.f16.f32 "
        "{%0,%1,%2,%3}, {%4,%5,%6,%7}, {%8,%9}, {%0,%1,%2,%3};"
        : "+f"(c[0]), "+f"(c[1]), "+f"(c[2]), "+f"(c[3])
        : "r"(a0), "r"(a1), "r"(a2), "r"(a3), "r"(b0), "r"(b1));
}
static __device__ __forceinline__ float leaky(float x) { return fmaxf(x, 0.1f * x); }

// no-op kernel: pads launch sequence so ncu -s5 capture lands on adj_hmma
__global__ void adj_dummy_kernel() {}

// ---------------------------------------------------------------------------
// Symmetric fp16-HMMA logits kernel. CTA = (batch, tile-pair ti<=tj, 64x64).
// 16 warps; warp w owns i-rows ti*64 + w*4 .. +3; 4 m-tiles of 16 j each.
// v tiles are stored in SMEM as half2; phi built with HSUB2+AND.
// ---------------------------------------------------------------------------
__global__ __launch_bounds__(THREADS, 1)
void adj_hmma_kernel(const float* __restrict__ v,
                     const float* __restrict__ W1, const float* __restrict__ b1,
                     const float* __restrict__ W2, const float* __restrict__ b2,
                     const float* __restrict__ W3, const float* __restrict__ b3,
                     float* __restrict__ out)
{
    extern __shared__ char sm[];
    uint32_t* VIh = (uint32_t*)(sm + OFF_VIH);
    uint32_t* VJh = (uint32_t*)(sm + OFF_VJH);
    uint32_t* W1F = (uint32_t*)(sm + OFF_W1F);
    uint32_t* W2F = (uint32_t*)(sm + OFF_W2F);

    const int tid  = threadIdx.x;
    const int wid  = tid >> 5;
    const int lane = tid & 31;
    const int g    = lane >> 2;   // groupID (row within fragment)
    const int t    = lane & 3;    // threadID_in_group
    const int b    = blockIdx.y;

    // decode (ti, tj), ti <= tj
    int rem = blockIdx.x;
    int ti = 0;
    while (rem >= NT - ti) { rem -= NT - ti; ti++; }
    const int tj = ti + rem;

    // ---- load v tiles (64 x 128 fp32), convert to half2, rows padded to 68 u32 ----
    const float* vb = v + (size_t)b * NN * DD;
    for (int e = tid; e < 64 * 32; e += THREADS) {
        int r = e >> 5, c = e & 31;   // c indexes float4 (4 ch = 2 half2)
        float4 xi = ((const float4*)(vb + (size_t)(ti * 64 + r) * DD))[c];
        float4 xj = ((const float4*)(vb + (size_t)(tj * 64 + r) * DD))[c];
        VIh[r * 68 + 2 * c]     = packh2(xi.x, xi.y);
        VIh[r * 68 + 2 * c + 1] = packh2(xi.z, xi.w);
        VJh[r * 68 + 2 * c]     = packh2(xj.x, xj.y);
        VJh[r * 68 + 2 * c + 1] = packh2(xj.z, xj.w);
    }
    // ---- W1 half2 fragments: [ks(8)][lane(32)][n(8)x{b0,b1}] ----
    for (int idx = tid; idx < 8 * 32 * 16; idx += THREADS) {
        int ks = idx >> 9, ln = (idx >> 4) & 31, rm = idx & 15;
        int n = rm >> 1, e = rm & 1;
        int o  = (ln >> 2) + 8 * n;
        int kb = 16 * ks + 2 * (ln & 3) + 8 * e;
        W1F[idx] = packh2(W1[o * DD + kb], W1[o * DD + kb + 1]);
    }
    // ---- W2 half2 fragments: [ks(4)][lane(32)][n(4)x{b0,b1}] ----
    for (int idx = tid; idx < 4 * 32 * 8; idx += THREADS) {
        int ks = idx >> 8, ln = (idx >> 3) & 31, rm = idx & 7;
        int n = rm >> 1, e = rm & 1;
        int o  = (ln >> 2) + 8 * n;
        int kb = 16 * ks + 2 * (ln & 3) + 8 * e;
        W2F[idx] = packh2(W2[o * H1C + kb], W2[o * H1C + kb + 1]);
    }
    // per-thread bias / w3 values at this thread's fragment columns
    float b1r[16], b2v[8], w3v[8];
    #pragma unroll
    for (int n = 0; n < 8; ++n) {
        b1r[2 * n]     = b1[8 * n + 2 * t];
        b1r[2 * n + 1] = b1[8 * n + 2 * t + 1];
    }
    #pragma unroll
    for (int n = 0; n < 4; ++n) {
        b2v[2 * n]     = b2[8 * n + 2 * t];
        b2v[2 * n + 1] = b2[8 * n + 2 * t + 1];
        w3v[2 * n]     = W3[8 * n + 2 * t];
        w3v[2 * n + 1] = W3[8 * n + 2 * t + 1];
    }
    const float bias3 = b3[0];
    __syncthreads();

    uint32_t* h1w = (uint32_t*)(sm + OFF_H1S) + wid * (16 * 36);
    float* ob = out + (size_t)b * NN * NN;

    for (int ii = 0; ii < 4; ++ii) {
        const int il = wid * 4 + ii;          // local i row
        const int ig = ti * 64 + il;          // global i

        // hoist this i-row's half2 values at this thread's k-positions
        uint32_t vilo[8], vihi[8];
        #pragma unroll
        for (int ks = 0; ks < 8; ++ks) {
            vilo[ks] = VIh[il * 68 + 8 * ks + t];       // ch 16ks+2t, +1
            vihi[ks] = VIh[il * 68 + 8 * ks + t + 4];   // ch 16ks+2t+8, +9
        }

        for (int jm = 0; jm < 4; ++jm) {
            const uint32_t* vj0 = VJh + (jm * 16 + g) * 68;
            const uint32_t* vj1 = VJh + (jm * 16 + 8 + g) * 68;

            // ---- GEMM1: h1[16j x 64] = |vi - vj| @ W1^T,  K = 128 ----
            float c1[8][4];
            #pragma unroll
            for (int n = 0; n < 8; ++n) {
                c1[n][0] = b1r[2 * n];     c1[n][1] = b1r[2 * n + 1];
                c1[n][2] = b1r[2 * n];     c1[n][3] = b1r[2 * n + 1];
            }

            #pragma unroll
            for (int ks = 0; ks < 8; ++ks) {
                uint32_t a0 = habs2_sub(vilo[ks], vj0[8 * ks + t]);
                uint32_t a1 = habs2_sub(vilo[ks], vj1[8 * ks + t]);
                uint32_t a2 = habs2_sub(vihi[ks], vj0[8 * ks + t + 4]);
                uint32_t a3 = habs2_sub(vihi[ks], vj1[8 * ks + t + 4]);
                const uint32_t* wq = W1F + ks * 512 + lane * 16;
                #pragma unroll
                for (int n = 0; n < 8; ++n)
                    mma_f16(c1[n], a0, a1, a2, a3, wq[2 * n], wq[2 * n + 1]);
            }

            // ---- leaky + pack adjacent channel pairs into per-warp scratch ----
            __syncwarp();
            #pragma unroll
            for (int n = 0; n < 8; ++n) {
                h1w[g * 36 + 4 * n + t]       = packh2(leaky(c1[n][0]), leaky(c1[n][1]));
                h1w[(g + 8) * 36 + 4 * n + t] = packh2(leaky(c1[n][2]), leaky(c1[n][3]));
            }
            __syncwarp();

            // ---- GEMM2: h2[16j x 32] = h1 @ W2^T,  K = 64 ----
            float c2[4][4];
            #pragma unroll
            for (int n = 0; n < 4; ++n) {
                c2[n][0] = b2v[2 * n];     c2[n][1] = b2v[2 * n + 1];
                c2[n][2] = b2v[2 * n];     c2[n][3] = b2v[2 * n + 1];
            }

            #pragma unroll
            for (int ks = 0; ks < 4; ++ks) {
                uint32_t a0 = h1w[g * 36 + 8 * ks + t];
                uint32_t a1 = h1w[(g + 8) * 36 + 8 * ks + t];
                uint32_t a2 = h1w[g * 36 + 8 * ks + t + 4];
                uint32_t a3 = h1w[(g + 8) * 36 + 8 * ks + t + 4];
                const uint32_t* wq = W2F + ks * 256 + lane * 8;
                #pragma unroll
                for (int n = 0; n < 4; ++n)
                    mma_f16(c2[n], a0, a1, a2, a3, wq[2 * n], wq[2 * n + 1]);
            }

            // ---- layer 3: logit = w3 . leaky(h2) + b3 (bias2 already in acc) ----
            float p0 = 0.0f, p1 = 0.0f;
            #pragma unroll
            for (int n = 0; n < 4; ++n) {
                p0 += leaky(c2[n][0]) * w3v[2 * n];
                p0 += leaky(c2[n][1]) * w3v[2 * n + 1];
                p1 += leaky(c2[n][2]) * w3v[2 * n];
                p1 += leaky(c2[n][3]) * w3v[2 * n + 1];
            }
            // reduce across the 4 threads of each row-group
            p0 += __shfl_xor_sync(0xFFFFFFFFu, p0, 1);
            p0 += __shfl_xor_sync(0xFFFFFFFFu, p0, 2);
            p1 += __shfl_xor_sync(0xFFFFFFFFu, p1, 1);
            p1 += __shfl_xor_sync(0xFFFFFFFFu, p1, 2);

            if (t == 0) {
                const int jg = tj * 64 + jm * 16 + g;
                float v0 = p0 + bias3, v1 = p1 + bias3;
                ob[(size_t)ig * NN + jg]     = v0;
                ob[(size_t)ig * NN + jg + 8] = v1;
                if (ti != tj) {   // mirror (logits exactly symmetric)
                    ob[(size_t)jg * NN + ig]       = v0;
                    ob[(size_t)(jg + 8) * NN + ig] = v1;
                }
            }
        }
    }
}

// ---------------------------------------------------------------------------
// Row softmax over last axis. One block per (b, i).
// ---------------------------------------------------------------------------
__global__ __launch_bounds__(256)
void adj_softmax_kernel(float* __restrict__ out)
{
    float* __restrict__ p = out + (size_t)blockIdx.x * NN;
    const int tid = threadIdx.x;

    float v0 = p[tid];
    float v1 = p[tid + 256];

    float m = fmaxf(v0, v1);
    #pragma unroll
    for (int o = 16; o; o >>= 1) m = fmaxf(m, __shfl_xor_sync(0xFFFFFFFFu, m, o));
    __shared__ float redm[8];
    if ((tid & 31) == 0) redm[tid >> 5] = m;
    __syncthreads();
    float M = redm[0];
    #pragma unroll
    for (int k = 1; k < 8; ++k) M = fmaxf(M, redm[k]);

    float e0 = __expf(v0 - M);
    float e1 = __expf(v1 - M);

    float s = e0 + e1;
    #pragma unroll
    for (int o = 16; o; o >>= 1) s += __shfl_xor_sync(0xFFFFFFFFu, s, o);
    __shared__ float reds[8];
    if ((tid & 31) == 0) reds[tid >> 5] = s;
    __syncthreads();
    float S = reds[0];
    #pragma unroll
    for (int k = 1; k < 8; ++k) S += reds[k];

    float inv = __fdividef(1.0f, S);
    p[tid]       = e0 * inv;
    p[tid + 256] = e1 * inv;
}

extern "C" void kernel_launch(void* const* d_in, const int* in_sizes, int n_in,
                              void* d_out, int out_size)
{
    const float* v  = (const float*)d_in[0];
    const float* W1 = (const float*)d_in[1];
    const float* b1 = (const float*)d_in[2];
    const float* W2 = (const float*)d_in[3];
    const float* b2 = (const float*)d_in[4];
    const float* W3 = (const float*)d_in[5];
    const float* b3 = (const float*)d_in[6];
    float* out = (float*)d_out;

    cudaFuncSetAttribute(adj_hmma_kernel,
                         cudaFuncAttributeMaxDynamicSharedMemorySize, SMEM_TOTAL);

    // order (hmma, softmax, dummy, dummy): previous round showed capture
    // lands on 0-based launch index 4 -> iteration-2's hmma kernel.
    dim3 grid(NPAIRS, NB);   // (36, 4) — one wave of 144 CTAs
    adj_hmma_kernel<<<grid, THREADS, SMEM_TOTAL>>>(v, W1, b1, W2, b2, W3, b3, out);
    adj_softmax_kernel<<<NB * NN, 256>>>(out);
    adj_dummy_kernel<<<1, 32>>>();
    adj_dummy_kernel<<<1, 32>>>();
}

// round 7
// speedup vs baseline: 7.6114x; 1.0606x over previous
#include <cuda_runtime.h>
#include <stdint.h>

#define NB 4
#define NN 512
#define DD 128
#define H1C 64
#define H2C 32
#define NT 8                       // 512/64 tiles
#define NPAIRS (NT * (NT + 1) / 2) // 36
#define THREADS 512

// ---- dynamic shared memory layout (bytes) ----
// VIh/VJh: 64 rows x 68 u32 (64 half2 data + 4 pad) each
#define OFF_VIH  0                 // 64*68*4 = 17408
#define OFF_VJH  17408             // 17408
#define OFF_W1F  34816             // 8 ks x 32 lane x 16 u32 = 16384
#define OFF_W2F  51200             // 4 ks x 32 lane x 8 u32 = 4096
#define SMEM_TOTAL 55296

static __device__ __forceinline__ uint32_t packh2(float lo, float hi) {
    uint32_t u;
    asm("cvt.rn.f16x2.f32 %0, %1, %2;" : "=r"(u) : "f"(hi), "f"(lo));
    return u;
}
static __device__ __forceinline__ uint32_t habs2_sub(uint32_t a, uint32_t b) {
    uint32_t d;
    asm("sub.f16x2 %0, %1, %2;" : "=r"(d) : "r"(a), "r"(b));
    return d & 0x7FFF7FFFu;
}
static __device__ __forceinline__ void mma_f16(float* c,
        uint32_t a0, uint32_t a1, uint32_t a2, uint32_t a3,
        uint32_t b0, uint32_t b1) {
    asm volatile(
        "mma.sync.aligned.m16n8k16.row.col.f32.f16.f16.f32 "
        "{%0,%1,%2,%3}, {%4,%5,%6,%7}, {%8,%9}, {%0,%1,%2,%3};"
        : "+f"(c[0]), "+f"(c[1]), "+f"(c[2]), "+f"(c[3])
        : "r"(a0), "r"(a1), "r"(a2), "r"(a3), "r"(b0), "r"(b1));
}
static __device__ __forceinline__ float leaky(float x) { return fmaxf(x, 0.1f * x); }

// ---------------------------------------------------------------------------
// Symmetric fp16-HMMA logits kernel. CTA = (batch, tile-pair ti<=tj, 64x64).
// 16 warps; warp w owns i-rows ti*64 + w*4 .. +3; 4 m-tiles of 16 j each.
// GEMM1 -> GEMM2 re-fragmentation is an identity map per thread: h1
// stays entirely in registers (no SMEM scratch, no syncwarp).
// ---------------------------------------------------------------------------
__global__ __launch_bounds__(THREADS, 1)
void adj_hmma_kernel(const float* __restrict__ v,
                     const float* __restrict__ W1, const float* __restrict__ b1,
                     const float* __restrict__ W2, const float* __restrict__ b2,
                     const float* __restrict__ W3, const float* __restrict__ b3,
                     float* __restrict__ out)
{
    extern __shared__ char sm[];
    uint32_t* VIh = (uint32_t*)(sm + OFF_VIH);
    uint32_t* VJh = (uint32_t*)(sm + OFF_VJH);
    uint32_t* W1F = (uint32_t*)(sm + OFF_W1F);
    uint32_t* W2F = (uint32_t*)(sm + OFF_W2F);

    const int tid  = threadIdx.x;
    const int wid  = tid >> 5;
    const int lane = tid & 31;
    const int g    = lane >> 2;   // groupID (row within fragment)
    const int t    = lane & 3;    // threadID_in_group
    const int b    = blockIdx.y;

    // decode (ti, tj), ti <= tj
    int rem = blockIdx.x;
    int ti = 0;
    while (rem >= NT - ti) { rem -= NT - ti; ti++; }
    const int tj = ti + rem;

    // ---- load v tiles (64 x 128 fp32), convert to half2, rows padded to 68 u32 ----
    const float* vb = v + (size_t)b * NN * DD;
    for (int e = tid; e < 64 * 32; e += THREADS) {
        int r = e >> 5, c = e & 31;   // c indexes float4 (4 ch = 2 half2)
        float4 xi = ((const float4*)(vb + (size_t)(ti * 64 + r) * DD))[c];
        float4 xj = ((const float4*)(vb + (size_t)(tj * 64 + r) * DD))[c];
        VIh[r * 68 + 2 * c]     = packh2(xi.x, xi.y);
        VIh[r * 68 + 2 * c + 1] = packh2(xi.z, xi.w);
        VJh[r * 68 + 2 * c]     = packh2(xj.x, xj.y);
        VJh[r * 68 + 2 * c + 1] = packh2(xj.z, xj.w);
    }
    // ---- W1 half2 fragments: [ks(8)][lane(32)][n(8)x{b0,b1}] ----
    for (int idx = tid; idx < 8 * 32 * 16; idx += THREADS) {
        int ks = idx >> 9, ln = (idx >> 4) & 31, rm = idx & 15;
        int n = rm >> 1, e = rm & 1;
        int o  = (ln >> 2) + 8 * n;
        int kb = 16 * ks + 2 * (ln & 3) + 8 * e;
        W1F[idx] = packh2(W1[o * DD + kb], W1[o * DD + kb + 1]);
    }
    // ---- W2 half2 fragments: [ks(4)][lane(32)][n(4)x{b0,b1}] ----
    for (int idx = tid; idx < 4 * 32 * 8; idx += THREADS) {
        int ks = idx >> 8, ln = (idx >> 3) & 31, rm = idx & 7;
        int n = rm >> 1, e = rm & 1;
        int o  = (ln >> 2) + 8 * n;
        int kb = 16 * ks + 2 * (ln & 3) + 8 * e;
        W2F[idx] = packh2(W2[o * H1C + kb], W2[o * H1C + kb + 1]);
    }
    // per-thread bias / w3 values at this thread's fragment columns
    float b1r[16], b2v[8], w3v[8];
    #pragma unroll
    for (int n = 0; n < 8; ++n) {
        b1r[2 * n]     = b1[8 * n + 2 * t];
        b1r[2 * n + 1] = b1[8 * n + 2 * t + 1];
    }
    #pragma unroll
    for (int n = 0; n < 4; ++n) {
        b2v[2 * n]     = b2[8 * n + 2 * t];
        b2v[2 * n + 1] = b2[8 * n + 2 * t + 1];
        w3v[2 * n]     = W3[8 * n + 2 * t];
        w3v[2 * n + 1] = W3[8 * n + 2 * t + 1];
    }
    const float bias3 = b3[0];
    __syncthreads();

    float* ob = out + (size_t)b * NN * NN;

    for (int ii = 0; ii < 4; ++ii) {
        const int il = wid * 4 + ii;          // local i row
        const int ig = ti * 64 + il;          // global i

        // hoist this i-row's half2 values at this thread's k-positions
        uint32_t vilo[8], vihi[8];
        #pragma unroll
        for (int ks = 0; ks < 8; ++ks) {
            vilo[ks] = VIh[il * 68 + 8 * ks + t];       // ch 16ks+2t, +1
            vihi[ks] = VIh[il * 68 + 8 * ks + t + 4];   // ch 16ks+2t+8, +9
        }

        for (int jm = 0; jm < 4; ++jm) {
            const uint32_t* vj0 = VJh + (jm * 16 + g) * 68;
            const uint32_t* vj1 = VJh + (jm * 16 + 8 + g) * 68;

            // ---- GEMM1: h1[16j x 64] = |vi - vj| @ W1^T,  K = 128 ----
            float c1[8][4];
            #pragma unroll
            for (int n = 0; n < 8; ++n) {
                c1[n][0] = b1r[2 * n];     c1[n][1] = b1r[2 * n + 1];
                c1[n][2] = b1r[2 * n];     c1[n][3] = b1r[2 * n + 1];
            }

            #pragma unroll
            for (int ks = 0; ks < 8; ++ks) {
                uint32_t a0 = habs2_sub(vilo[ks], vj0[8 * ks + t]);
                uint32_t a1 = habs2_sub(vilo[ks], vj1[8 * ks + t]);
                uint32_t a2 = habs2_sub(vihi[ks], vj0[8 * ks + t + 4]);
                uint32_t a3 = habs2_sub(vihi[ks], vj1[8 * ks + t + 4]);
                const uint32_t* wq = W1F + ks * 512 + lane * 16;
                #pragma unroll
                for (int n = 0; n < 8; ++n)
                    mma_f16(c1[n], a0, a1, a2, a3, wq[2 * n], wq[2 * n + 1]);
            }

            // ---- GEMM2: h2[16j x 32] = leaky(h1) @ W2^T,  K = 64 ----
            // A-fragments come straight from c1 (identity re-fragmentation):
            //   ks -> a0 = rows g,   ch 16ks+2t,+1  = c1[2ks][0..1]
            //         a1 = rows g+8, ch 16ks+2t,+1  = c1[2ks][2..3]
            //         a2 = rows g,   ch 16ks+8+2t,+1= c1[2ks+1][0..1]
            //         a3 = rows g+8, ch 16ks+8+2t,+1= c1[2ks+1][2..3]
            float c2[4][4];
            #pragma unroll
            for (int n = 0; n < 4; ++n) {
                c2[n][0] = b2v[2 * n];     c2[n][1] = b2v[2 * n + 1];
                c2[n][2] = b2v[2 * n];     c2[n][3] = b2v[2 * n + 1];
            }

            #pragma unroll
            for (int ks = 0; ks < 4; ++ks) {
                uint32_t a0 = packh2(leaky(c1[2 * ks][0]),     leaky(c1[2 * ks][1]));
                uint32_t a1 = packh2(leaky(c1[2 * ks][2]),     leaky(c1[2 * ks][3]));
                uint32_t a2 = packh2(leaky(c1[2 * ks + 1][0]), leaky(c1[2 * ks + 1][1]));
                uint32_t a3 = packh2(leaky(c1[2 * ks + 1][2]), leaky(c1[2 * ks + 1][3]));
                const uint32_t* wq = W2F + ks * 256 + lane * 8;
                #pragma unroll
                for (int n = 0; n < 4; ++n)
                    mma_f16(c2[n], a0, a1, a2, a3, wq[2 * n], wq[2 * n + 1]);
            }

            // ---- layer 3: logit = w3 . leaky(h2) + b3 (bias2 already in acc) ----
            float p0 = 0.0f, p1 = 0.0f;
            #pragma unroll
            for (int n = 0; n < 4; ++n) {
                p0 += leaky(c2[n][0]) * w3v[2 * n];
                p0 += leaky(c2[n][1]) * w3v[2 * n + 1];
                p1 += leaky(c2[n][2]) * w3v[2 * n];
                p1 += leaky(c2[n][3]) * w3v[2 * n + 1];
            }
            // reduce across the 4 threads of each row-group
            p0 += __shfl_xor_sync(0xFFFFFFFFu, p0, 1);
            p0 += __shfl_xor_sync(0xFFFFFFFFu, p0, 2);
            p1 += __shfl_xor_sync(0xFFFFFFFFu, p1, 1);
            p1 += __shfl_xor_sync(0xFFFFFFFFu, p1, 2);

            if (t == 0) {
                const int jg = tj * 64 + jm * 16 + g;
                float v0 = p0 + bias3, v1 = p1 + bias3;
                ob[(size_t)ig * NN + jg]     = v0;
                ob[(size_t)ig * NN + jg + 8] = v1;
                if (ti != tj) {   // mirror (logits exactly symmetric)
                    ob[(size_t)jg * NN + ig]       = v0;
                    ob[(size_t)(jg + 8) * NN + ig] = v1;
                }
            }
        }
    }
}

// ---------------------------------------------------------------------------
// Row softmax over last axis. One block (128 thr) per (b, i); float4 I/O.
// ---------------------------------------------------------------------------
__global__ __launch_bounds__(128)
void adj_softmax_kernel(float* __restrict__ out)
{
    float4* __restrict__ p = (float4*)(out + (size_t)blockIdx.x * NN);
    const int tid = threadIdx.x;

    float4 x = p[tid];

    float m = fmaxf(fmaxf(x.x, x.y), fmaxf(x.z, x.w));
    #pragma unroll
    for (int o = 16; o; o >>= 1) m = fmaxf(m, __shfl_xor_sync(0xFFFFFFFFu, m, o));
    __shared__ float redm[4];
    if ((tid & 31) == 0) redm[tid >> 5] = m;
    __syncthreads();
    float M = fmaxf(fmaxf(redm[0], redm[1]), fmaxf(redm[2], redm[3]));

    float4 e;
    e.x = __expf(x.x - M);
    e.y = __expf(x.y - M);
    e.z = __expf(x.z - M);
    e.w = __expf(x.w - M);

    float s = (e.x + e.y) + (e.z + e.w);
    #pragma unroll
    for (int o = 16; o; o >>= 1) s += __shfl_xor_sync(0xFFFFFFFFu, s, o);
    __shared__ float reds[4];
    if ((tid & 31) == 0) reds[tid >> 5] = s;
    __syncthreads();
    float S = (reds[0] + reds[1]) + (reds[2] + reds[3]);

    float inv = __fdividef(1.0f, S);
    e.x *= inv; e.y *= inv; e.z *= inv; e.w *= inv;
    p[tid] = e;
}

extern "C" void kernel_launch(void* const* d_in, const int* in_sizes, int n_in,
                              void* d_out, int out_size)
{
    const float* v  = (const float*)d_in[0];
    const float* W1 = (const float*)d_in[1];
    const float* b1 = (const float*)d_in[2];
    const float* W2 = (const float*)d_in[3];
    const float* b2 = (const float*)d_in[4];
    const float* W3 = (const float*)d_in[5];
    const float* b3 = (const float*)d_in[6];
    float* out = (float*)d_out;

    cudaFuncSetAttribute(adj_hmma_kernel,
                         cudaFuncAttributeMaxDynamicSharedMemorySize, SMEM_TOTAL);

    dim3 grid(NPAIRS, NB);   // (36, 4) — one wave of 144 CTAs
    adj_hmma_kernel<<<grid, THREADS, SMEM_TOTAL>>>(v, W1, b1, W2, b2, W3, b3, out);
    adj_softmax_kernel<<<NB * NN, 128>>>(out);
}